// round 16
// baseline (speedup 1.0000x reference)
#include <cuda_runtime.h>

typedef unsigned long long ull;

#define TT 16
#define DD 8
#define HH 40
#define HP1 41
#define NT 64
#define NTHREADS 512
#define NBLK 296
#define NPAIR_PAD 1024
#define NPAIRS 948
#define PPT 2
#define WSTRIDE 52

// Output offsets (reference tuple order, row-major each)
#define O_BG1 0
#define O_BG2 16
#define O_MU  32
#define O_KAP 160
#define O_NU  176
#define O_PSI 192
#define O_WM  1216
#define O_WS  1872
#define O_ZA  28768
#define O_ZB  28784
#define O_EA  28800
#define O_EB  28816

__device__ ull    g_part[(size_t)NBLK * NPAIR_PAD * 8];
__device__ float2 g_tot[NPAIR_PAD * TT];

// ---------------- double-float helpers (all full-rate fp32) ----------------
struct dfv { float h, l; };
__device__ __forceinline__ dfv two_sum(float a, float b) {
    float s = a + b;
    float bb = s - a;
    float e = (a - (s - bb)) + (b - bb);
    dfv r; r.h = s; r.l = e; return r;
}
__device__ __forceinline__ dfv df_norm(float h, float l) {
    float s = h + l;
    float e = l - (s - h);
    dfv r; r.h = s; r.l = e; return r;
}
__device__ __forceinline__ dfv df_add(dfv a, dfv b) {
    dfv s = two_sum(a.h, b.h);
    return df_norm(s.h, s.l + a.l + b.l);
}
__device__ __forceinline__ dfv df_addf(dfv a, float b) {
    dfv s = two_sum(a.h, b);
    return df_norm(s.h, s.l + a.l);
}
__device__ __forceinline__ dfv df_mul(dfv a, dfv b) {
    float p = a.h * b.h;
    float e = fmaf(a.h, b.h, -p);
    e = fmaf(a.h, b.l, e);
    e = fmaf(a.l, b.h, e);
    return df_norm(p, e);
}
__device__ __forceinline__ dfv df_mulf(dfv a, float b) {
    float p = a.h * b;
    float e = fmaf(a.h, b, -p);
    e = fmaf(a.l, b, e);
    return df_norm(p, e);
}
__device__ __forceinline__ dfv dtot(int idx) {
    float2 v = g_tot[idx];
    dfv r; r.h = v.x; r.l = v.y; return r;
}

__device__ __forceinline__ void pair_of(int p, int &wi, int &wj) {
    if (p < 45) {
        int i = 0, rem = p;
        while (rem >= 9 - i) { rem -= 9 - i; ++i; }
        wi = i; wj = i + rem;
    } else if (p < NPAIRS) {
        int q = p - 45, a = 0;
        while (q >= 42 - a) { q -= 42 - a; ++a; }
        wi = 8 + a; wj = 8 + a + q;
    } else {
        wi = 50; wj = 50;
    }
}

__device__ __forceinline__ int pairM1(int i, int j) { return i*9 - (i*(i-1))/2 + (j - i); }
__device__ __forceinline__ int pairM2(int a, int b) { return 45 + a*42 - (a*(a-1))/2 + (b - a); }
__device__ __forceinline__ int lmap(int i) { return (i < HH) ? (i + 1) : 0; }

// Same slot->pair map and per-slot accumulation order as the 256-thr/PPT=4
// version: slot = tid*PPT + k enumerates 0..1023, each slot owned by exactly
// one thread, same row order, same FFMA2 chain -> g_part bitwise identical.
__global__ __launch_bounds__(NTHREADS, 2) void k_reduce(
    const float* __restrict__ Phi, const float* __restrict__ Xin,
    const float* __restrict__ Yout, const float* __restrict__ Welm,
    const float* __restrict__ Belm, int n_total)
{
    __shared__ __align__(16) float ws[NT][WSTRIDE];
    __shared__ __align__(16) float phs[NT][TT];
    __shared__ float sW[DD*HH];
    __shared__ float sB[HH];
    const int tid = threadIdx.x;

    for (int i = tid; i < DD*HH; i += NTHREADS) sW[i] = Welm[i];
    if (tid < HH) sB[tid] = Belm[tid];

    int wi[PPT], wj[PPT];
#pragma unroll
    for (int k = 0; k < PPT; ++k) pair_of(tid*PPT + k, wi[k], wj[k]);

    ull acc[PPT][8];
#pragma unroll
    for (int k = 0; k < PPT; ++k)
#pragma unroll
        for (int w = 0; w < 8; ++w) acc[k][w] = 0ull;

    const int stride = NT * gridDim.x;
    const int ntiles = (n_total + stride - 1) / stride;

    for (int tile = 0; tile < ntiles; ++tile) {
        const int n0 = (blockIdx.x + tile * gridDim.x) * NT;
        // Padding-only tile: phi rows all-zero -> contributions exactly +0.0.
        if (n0 >= n_total) break;
        __syncthreads();
        for (int idx = tid; idx < NT*DD; idx += NTHREADS) {
            int r = idx >> 3;
            float v = (n0 + r < n_total) ? Xin[(size_t)n0*DD + idx] : 0.f;
            ws[r][idx & 7] = v;
        }
        for (int idx = tid; idx < NT*TT; idx += NTHREADS) {
            int r = idx >> 4;
            float v = (n0 + r < n_total) ? Phi[(size_t)n0*TT + idx] : 0.f;
            phs[r][idx & 15] = v;
        }
        for (int r = tid; r < NT; r += NTHREADS) {
            ws[r][8]  = 1.0f;
            ws[r][49] = (n0 + r < n_total) ? Yout[n0 + r] : 0.f;
            ws[r][50] = 0.f; ws[r][51] = 0.f;
        }
        __syncthreads();
        for (int q = tid; q < NT*HH; q += NTHREADS) {
            int r = q / HH, h = q - r*HH;
            float z = sB[h];
#pragma unroll
            for (int d = 0; d < DD; ++d) z = fmaf(ws[r][d], sW[d*HH + h], z);
            ws[r][9 + h] = 1.0f / (1.0f + __expf(-z));
        }
        __syncthreads();

#pragma unroll 2
        for (int r = 0; r < NT; ++r) {
            // phi row as 4x LDS.128 (rows are 64B, 16B-aligned)
            const ulonglong2* ph2 = reinterpret_cast<const ulonglong2*>(&phs[r][0]);
            ulonglong2 qa = ph2[0], qb = ph2[1], qc = ph2[2], qd = ph2[3];
            const float* row = &ws[r][0];
#pragma unroll
            for (int k = 0; k < PPT; ++k) {
                float prod = row[wi[k]] * row[wj[k]];
                unsigned int pu = __float_as_uint(prod);
                ull pp;
                asm("mov.b64 %0, {%1, %2};" : "=l"(pp) : "r"(pu), "r"(pu));
                asm("fma.rn.f32x2 %0, %1, %2, %0;" : "+l"(acc[k][0]) : "l"(qa.x), "l"(pp));
                asm("fma.rn.f32x2 %0, %1, %2, %0;" : "+l"(acc[k][1]) : "l"(qa.y), "l"(pp));
                asm("fma.rn.f32x2 %0, %1, %2, %0;" : "+l"(acc[k][2]) : "l"(qb.x), "l"(pp));
                asm("fma.rn.f32x2 %0, %1, %2, %0;" : "+l"(acc[k][3]) : "l"(qb.y), "l"(pp));
                asm("fma.rn.f32x2 %0, %1, %2, %0;" : "+l"(acc[k][4]) : "l"(qc.x), "l"(pp));
                asm("fma.rn.f32x2 %0, %1, %2, %0;" : "+l"(acc[k][5]) : "l"(qc.y), "l"(pp));
                asm("fma.rn.f32x2 %0, %1, %2, %0;" : "+l"(acc[k][6]) : "l"(qd.x), "l"(pp));
                asm("fma.rn.f32x2 %0, %1, %2, %0;" : "+l"(acc[k][7]) : "l"(qd.y), "l"(pp));
            }
        }
    }

    ull* outp = &g_part[((size_t)blockIdx.x * NPAIR_PAD + (size_t)tid*PPT) * 8];
#pragma unroll
    for (int k = 0; k < PPT; ++k)
#pragma unroll
        for (int w = 0; w < 8; ++w) outp[k*8 + w] = acc[k][w];
}

// Coalesced parallel compensated cross-block sum.
// warp = one fixed partial q (b = q, q+8, ...), lanes = 32 consecutive e
// -> every LDG is a single 128B line. Combine the 8 partials per e in shared
// memory with the SAME fixed tree as before -> g_tot bitwise identical.
__global__ __launch_bounds__(256) void k_sum(int nblk) {
    __shared__ float smh[8][33], sml[8][33];
    const int l = threadIdx.x & 31;        // lane -> e offset
    const int q = threadIdx.x >> 5;        // warp -> partial index
    const int e0 = blockIdx.x * 32;
    const int e = e0 + l;
    const float* pf = reinterpret_cast<const float*>(g_part);
    float sh = 0.f, sl = 0.f;
    for (int b = q; b < nblk; b += 8) {
        float x = pf[(size_t)b * (NPAIR_PAD*TT) + e];
        float s = sh + x;
        float bb = s - sh;
        float err = (sh - (s - bb)) + (x - bb);
        sh = s; sl += err;
    }
    smh[q][l] = sh; sml[q][l] = sl;
    __syncthreads();
    if (threadIdx.x < 32) {
        dfv a0; a0.h = smh[0][l]; a0.l = sml[0][l];
        dfv a1; a1.h = smh[1][l]; a1.l = sml[1][l];
        dfv a2; a2.h = smh[2][l]; a2.l = sml[2][l];
        dfv a3; a3.h = smh[3][l]; a3.l = sml[3][l];
        dfv a4; a4.h = smh[4][l]; a4.l = sml[4][l];
        dfv a5; a5.h = smh[5][l]; a5.l = sml[5][l];
        dfv a6; a6.h = smh[6][l]; a6.l = sml[6][l];
        dfv a7; a7.h = smh[7][l]; a7.l = sml[7][l];
        dfv b01 = df_add(a0, a1);
        dfv b23 = df_add(a2, a3);
        dfv b45 = df_add(a4, a5);
        dfv b67 = df_add(a6, a7);
        dfv c03 = df_add(b01, b23);
        dfv c47 = df_add(b45, b67);
        dfv tt  = df_add(c03, c47);
        g_tot[e] = make_float2(tt.h, tt.l);
    }
}

#define NF 512

__global__ __launch_bounds__(NF) void k_final(
    const float* __restrict__ epsA, const float* __restrict__ epsB,
    const float* __restrict__ zetA, const float* __restrict__ zetB,
    float* __restrict__ out)
{
    const int t = blockIdx.x;
    const int tid = threadIdx.x;
    __shared__ float Mh[HP1][HP1+1], Ml[HP1][HP1+1];
    __shared__ float Xs[HP1][HP1+1];   // GJ inverse / Newton ping buffer (final lands here)
    __shared__ float Rs[HP1][HP1+1];
    __shared__ float Ts[HP1][HP1+1];   // Newton pong buffer
    __shared__ float rowkb[2][HP1], colkb[2][HP1];   // ping-pong pivot row/col
    __shared__ float bvh[HP1], bvl[HP1], wmv[HP1];
    __shared__ float4 red[NF/32];

    const float eps = __fdiv_rn(epsA[t], epsB[t]);
    const float zet = __fdiv_rn(zetA[t], zetB[t]);

    // Per-thread flat element list for 41x41 sweeps
    int er[4], ec[4];
#pragma unroll
    for (int u = 0; u < 4; ++u) {
        int idx = tid + u*NF;
        if (idx < HP1*HP1) { er[u] = idx / HP1; ec[u] = idx - er[u]*HP1; }
        else { er[u] = -1; ec[u] = 0; }
    }

    // Per-t slice of the cheap outputs
    if (tid == 0) {
        dfv sp = dtot(44*TT + t);
        out[O_BG1 + t] = df_addf(sp, 1.0f).h;
        out[O_KAP + t] = df_addf(sp, 1000.0f).h;
        out[O_NU  + t] = df_addf(sp, 100.0f).h;
        out[O_ZA  + t] = zetA[t] + 20.5f;
        out[O_EA  + t] = df_addf(df_mulf(sp, 0.5f), epsA[t]).h;
        dfv s2; s2.h = 0.f; s2.l = 0.f;
        for (int v = t + 1; v < TT; ++v) s2 = df_add(s2, dtot(44*TT + v));
        out[O_BG2 + t] = df_addf(s2, 1.0f).h;
    }
    if (tid >= 32 && tid < 32 + DD) {
        int i = tid - 32;
        dfv kap = df_addf(dtot(44*TT + t), 1000.0f);
        out[O_MU + i*TT + t] = __fdiv_rn(dtot(pairM1(i,8)*TT + t).h, kap.h);
    }
    if (tid >= 64 && tid < 128) {
        int i = (tid - 64) >> 3, j = (tid - 64) & 7;
        dfv kap = df_addf(dtot(44*TT + t), 1000.0f);
        dfv t12i = dtot(pairM1(i,8)*TT + t);
        dfv t12j = dtot(pairM1(j,8)*TT + t);
        int lo = i < j ? i : j, hi = i < j ? j : i;
        dfv Sij = dtot(pairM1(lo,hi)*TT + t);
        dfv num = df_mul(t12i, t12j);
        float q0 = __fdiv_rn(num.h, kap.h);
        dfv rem = df_add(num, df_mulf(kap, -q0));
        float q1 = __fdiv_rn(rem.h + rem.l, kap.h);
        dfv s1 = two_sum(Sij.h, -q0);
        float psi = s1.h + (s1.l + Sij.l - q1) + ((i==j) ? 500.0f : 0.0f);
        out[O_PSI + i*DD*TT + j*TT + t] = psi;
    }

    // Build M (double-float): M = eps*A + zet*I ; Xs = fp32 copy for in-place GJ.
    // Also seed the k=0 pivot row/col buffers (parity 0).
#pragma unroll
    for (int u = 0; u < 4; ++u) {
        if (er[u] < 0) continue;
        int i = er[u], j = ec[u];
        int a = lmap(i), b = lmap(j);
        int lo = a < b ? a : b, hi = a < b ? b : a;
        dfv A = dtot(pairM2(lo, hi)*TT + t);
        dfv M = df_mulf(A, eps);
        if (i == j) M = df_addf(M, zet);
        Mh[i][j] = M.h; Ml[i][j] = M.l;
        Xs[i][j] = M.h;
        if (i == 0) rowkb[0][j] = M.h;
        if (j == 0) colkb[0][i] = M.h;
    }
    __syncthreads();

    // In-place pivot-free Gauss-Jordan inversion (M is SPD), ONE sync/iter:
    // sweep k also mirrors the freshly-computed row/col k+1 into ping-pong buffers.
    for (int k = 0; k < HP1; ++k) {
        const int pb = k & 1, nb = pb ^ 1;
        float ip = __frcp_rn(rowkb[pb][k]);
#pragma unroll
        for (int u = 0; u < 4; ++u) {
            if (er[u] < 0) continue;
            int r = er[u], c = ec[u];
            float v;
            if (r == k) {
                v = (c == k) ? ip : rowkb[pb][c] * ip;
            } else {
                float f = colkb[pb][r] * ip;
                v = (c == k) ? -f : fmaf(-f, rowkb[pb][c], Xs[r][c]);
            }
            Xs[r][c] = v;
            if (r == k + 1) rowkb[nb][c] = v;
            if (c == k + 1) colkb[nb][r] = v;
        }
        __syncthreads();
    }

    // 2 Newton steps, ping-pong (2 syncs/iter): R = I - M*X ; Xnext = X + X*R
    {
        float (*Xc)[HP1+1] = Xs;
        float (*Xn)[HP1+1] = Ts;
        for (int it = 0; it < 2; ++it) {
#pragma unroll
            for (int u = 0; u < 4; ++u) {
                if (er[u] < 0) continue;
                int i = er[u], j = ec[u];
                float sh = 0.f, sl = 0.f;
                for (int k = 0; k < HP1; ++k) {
                    float mh = Mh[i][k], x = Xc[k][j];
                    float p = mh * x;
                    float e = fmaf(mh, x, -p);
                    e = fmaf(Ml[i][k], x, e);
                    float s = sh + p;
                    float bb = s - sh;
                    float err = (sh - (s - bb)) + (p - bb);
                    sh = s; sl += err + e;
                }
                float d = (i==j) ? 1.f : 0.f;
                dfv r = two_sum(d, -sh);
                Rs[i][j] = r.h + (r.l - sl);
            }
            __syncthreads();
#pragma unroll
            for (int u = 0; u < 4; ++u) {
                if (er[u] < 0) continue;
                int i = er[u], j = ec[u];
                float s = Xc[i][j];
                for (int k = 0; k < HP1; ++k) s = fmaf(Xc[i][k], Rs[k][j], s);
                Xn[i][j] = s;
            }
            __syncthreads();
            float (*tmp)[HP1+1] = Xc; Xc = Xn; Xn = tmp;
        }
        // after 2 iters the final inverse is back in Xs
    }

    // b vector (df) and WMv = zet * X b  (df dot)
    if (tid < HP1) {
        dfv b = dtot(pairM2(lmap(tid), HP1)*TT + t);
        bvh[tid] = b.h; bvl[tid] = b.l;
    }
    __syncthreads();
    if (tid < HP1) {
        float sh = 0.f, sl = 0.f;
        for (int j = 0; j < HP1; ++j) {
            float x = Xs[tid][j];
            float p = x * bvh[j];
            float e = fmaf(x, bvh[j], -p);
            e = fmaf(x, bvl[j], e);
            float s = sh + p;
            float bb = s - sh;
            float err = (sh - (s - bb)) + (p - bb);
            sh = s; sl += err + e;
        }
        float wm = zet * (sh + sl);
        wmv[tid] = wm;
        out[O_WM + t*HP1 + tid] = wm;
    }
    __syncthreads();

#pragma unroll
    for (int u = 0; u < 4; ++u) {
        if (er[u] < 0) continue;
        out[O_WS + t*HP1*HP1 + er[u]*HP1 + ec[u]] = Xs[er[u]][ec[u]];
    }

    // Epilogue partials: t2e = sum_ij M_ij X_ji ; wMw = sum_ij wm_i M_ij wm_j
    float ah = 0.f, al = 0.f, bh2 = 0.f, bl2 = 0.f;
#pragma unroll
    for (int u = 0; u < 4; ++u) {
        if (er[u] < 0) continue;
        int i = er[u], j = ec[u];
        float mh = Mh[i][j], ml = Ml[i][j];
        float x = Xs[j][i];
        float p = mh * x;
        float e = fmaf(mh, x, -p);
        e = fmaf(ml, x, e);
        { float s = ah + p; float bb = s - ah;
          float err = (ah - (s - bb)) + (p - bb);
          ah = s; al += err + e; }
        float w2 = wmv[i] * wmv[j];
        float p2 = mh * w2;
        float e2 = fmaf(mh, w2, -p2);
        e2 = fmaf(ml, w2, e2);
        { float s = bh2 + p2; float bb = s - bh2;
          float err = (bh2 - (s - bb)) + (p2 - bb);
          bh2 = s; bl2 += err + e2; }
    }
    {
        dfv a; a.h = ah; a.l = al;
        dfv b; b.h = bh2; b.l = bl2;
#pragma unroll
        for (int off = 16; off > 0; off >>= 1) {
            float xh = __shfl_down_sync(0xffffffffu, a.h, off);
            float xl = __shfl_down_sync(0xffffffffu, a.l, off);
            float yh = __shfl_down_sync(0xffffffffu, b.h, off);
            float yl = __shfl_down_sync(0xffffffffu, b.l, off);
            dfv xa; xa.h = xh; xa.l = xl;
            dfv yb; yb.h = yh; yb.l = yl;
            a = df_add(a, xa);
            b = df_add(b, yb);
        }
        if ((tid & 31) == 0) red[tid >> 5] = make_float4(a.h, a.l, b.h, b.l);
    }
    __syncthreads();

    if (tid == 0) {
        dfv t2e; t2e.h = 0.f; t2e.l = 0.f;
        dfv wMw; wMw.h = 0.f; wMw.l = 0.f;
        for (int k = 0; k < NF/32; ++k) {
            float4 v = red[k];
            dfv a; a.h = v.x; a.l = v.y;
            dfv b; b.h = v.z; b.l = v.w;
            t2e = df_add(t2e, a);
            wMw = df_add(wMw, b);
        }
        dfv trX; trX.h = 0.f; trX.l = 0.f;
        dfv wm2; wm2.h = 0.f; wm2.l = 0.f;
        dfv wb;  wb.h = 0.f;  wb.l = 0.f;
        for (int i = 0; i < HP1; ++i) {
            trX = df_addf(trX, Xs[i][i]);
            float w = wmv[i];
            dfv ww; ww.h = w * w; ww.l = fmaf(w, w, -ww.h);
            wm2 = df_add(wm2, ww);
            dfv bvi; bvi.h = bvh[i]; bvi.l = bvl[i];
            wb = df_add(wb, df_mulf(bvi, w));
        }
        float inv_eps = __frcp_rn(eps);
        dfv t2 = df_mulf(df_add(t2e, df_mulf(trX, -zet)), inv_eps);
        dfv qf = df_mulf(df_add(wMw, df_mulf(wm2, -zet)), inv_eps);
        dfv cc = dtot(947*TT + t);
        dfv t1 = df_add(df_add(cc, df_mulf(wb, -2.0f)), qf);
        dfv zb = df_addf(df_mulf(df_add(wm2, trX), 0.5f), zetB[t]);
        dfv eb = df_addf(df_mulf(df_add(t1, t2), 0.5f), epsB[t]);
        out[O_ZB + t] = zb.h;
        out[O_EB + t] = eb.h;
    }
}

extern "C" void kernel_launch(void* const* d_in, const int* in_sizes, int n_in,
                              void* d_out, int out_size) {
    const float* Phi  = (const float*)d_in[1];
    const float* Xin  = (const float*)d_in[2];
    const float* Yout = (const float*)d_in[3];
    const float* W    = (const float*)d_in[4];
    const float* B    = (const float*)d_in[5];
    const float* eA   = (const float*)d_in[6];
    const float* eB   = (const float*)d_in[7];
    const float* zA   = (const float*)d_in[8];
    const float* zB   = (const float*)d_in[9];
    int n_total = in_sizes[1] / TT;

    k_reduce<<<NBLK, NTHREADS>>>(Phi, Xin, Yout, W, B, n_total);
    k_sum<<<(NPAIR_PAD*TT)/32, 256>>>(NBLK);
    k_final<<<TT, NF>>>(eA, eB, zA, zB, (float*)d_out);
}

// round 17
// speedup vs baseline: 1.0744x; 1.0744x over previous
#include <cuda_runtime.h>

typedef unsigned long long ull;

#define TT 16
#define DD 8
#define HH 40
#define HP1 41
#define NT 64
#define NTHREADS 256
#define NBLK 296
#define NPAIR_PAD 1024
#define NPAIRS 948
#define PPT 4
#define WSTRIDE 52

// Output offsets (reference tuple order, row-major each)
#define O_BG1 0
#define O_BG2 16
#define O_MU  32
#define O_KAP 160
#define O_NU  176
#define O_PSI 192
#define O_WM  1216
#define O_WS  1872
#define O_ZA  28768
#define O_ZB  28784
#define O_EA  28800
#define O_EB  28816

__device__ ull    g_part[(size_t)NBLK * NPAIR_PAD * 8];
__device__ float2 g_tot[NPAIR_PAD * TT];

// ---------------- double-float helpers (all full-rate fp32) ----------------
struct dfv { float h, l; };
__device__ __forceinline__ dfv two_sum(float a, float b) {
    float s = a + b;
    float bb = s - a;
    float e = (a - (s - bb)) + (b - bb);
    dfv r; r.h = s; r.l = e; return r;
}
__device__ __forceinline__ dfv df_norm(float h, float l) {
    float s = h + l;
    float e = l - (s - h);
    dfv r; r.h = s; r.l = e; return r;
}
__device__ __forceinline__ dfv df_add(dfv a, dfv b) {
    dfv s = two_sum(a.h, b.h);
    return df_norm(s.h, s.l + a.l + b.l);
}
__device__ __forceinline__ dfv df_addf(dfv a, float b) {
    dfv s = two_sum(a.h, b);
    return df_norm(s.h, s.l + a.l);
}
__device__ __forceinline__ dfv df_mul(dfv a, dfv b) {
    float p = a.h * b.h;
    float e = fmaf(a.h, b.h, -p);
    e = fmaf(a.h, b.l, e);
    e = fmaf(a.l, b.h, e);
    return df_norm(p, e);
}
__device__ __forceinline__ dfv df_mulf(dfv a, float b) {
    float p = a.h * b;
    float e = fmaf(a.h, b, -p);
    e = fmaf(a.l, b, e);
    return df_norm(p, e);
}
__device__ __forceinline__ dfv dtot(int idx) {
    float2 v = g_tot[idx];
    dfv r; r.h = v.x; r.l = v.y; return r;
}

__device__ __forceinline__ void pair_of(int p, int &wi, int &wj) {
    if (p < 45) {
        int i = 0, rem = p;
        while (rem >= 9 - i) { rem -= 9 - i; ++i; }
        wi = i; wj = i + rem;
    } else if (p < NPAIRS) {
        int q = p - 45, a = 0;
        while (q >= 42 - a) { q -= 42 - a; ++a; }
        wi = 8 + a; wj = 8 + a + q;
    } else {
        wi = 50; wj = 50;
    }
}

__device__ __forceinline__ int pairM1(int i, int j) { return i*9 - (i*(i-1))/2 + (j - i); }
__device__ __forceinline__ int pairM2(int a, int b) { return 45 + a*42 - (a*(a-1))/2 + (b - a); }
__device__ __forceinline__ int lmap(int i) { return (i < HH) ? (i + 1) : 0; }

__global__ __launch_bounds__(NTHREADS, 2) void k_reduce(
    const float* __restrict__ Phi, const float* __restrict__ Xin,
    const float* __restrict__ Yout, const float* __restrict__ Welm,
    const float* __restrict__ Belm, int n_total)
{
    __shared__ __align__(16) float ws[NT][WSTRIDE];
    __shared__ __align__(16) float phs[NT][TT];
    __shared__ float sW[DD*HH];
    __shared__ float sB[HH];
    const int tid = threadIdx.x;

    for (int i = tid; i < DD*HH; i += NTHREADS) sW[i] = Welm[i];
    if (tid < HH) sB[tid] = Belm[tid];

    int wi[PPT], wj[PPT];
#pragma unroll
    for (int k = 0; k < PPT; ++k) pair_of(tid*PPT + k, wi[k], wj[k]);

    ull acc[PPT][8];
#pragma unroll
    for (int k = 0; k < PPT; ++k)
#pragma unroll
        for (int w = 0; w < 8; ++w) acc[k][w] = 0ull;

    const int stride = NT * gridDim.x;
    const int ntiles = (n_total + stride - 1) / stride;

    for (int tile = 0; tile < ntiles; ++tile) {
        const int n0 = (blockIdx.x + tile * gridDim.x) * NT;
        // Padding-only tile for this block: phi rows would be all-zero, so the
        // FFMA2 contributions are exactly +0.0. Skipping is bitwise-neutral.
        if (n0 >= n_total) break;
        __syncthreads();
        for (int idx = tid; idx < NT*DD; idx += NTHREADS) {
            int r = idx >> 3;
            float v = (n0 + r < n_total) ? Xin[(size_t)n0*DD + idx] : 0.f;
            ws[r][idx & 7] = v;
        }
        for (int idx = tid; idx < NT*TT; idx += NTHREADS) {
            int r = idx >> 4;
            float v = (n0 + r < n_total) ? Phi[(size_t)n0*TT + idx] : 0.f;
            phs[r][idx & 15] = v;
        }
        for (int r = tid; r < NT; r += NTHREADS) {
            ws[r][8]  = 1.0f;
            ws[r][49] = (n0 + r < n_total) ? Yout[n0 + r] : 0.f;
            ws[r][50] = 0.f; ws[r][51] = 0.f;
        }
        __syncthreads();
        for (int q = tid; q < NT*HH; q += NTHREADS) {
            int r = q / HH, h = q - r*HH;
            float z = sB[h];
#pragma unroll
            for (int d = 0; d < DD; ++d) z = fmaf(ws[r][d], sW[d*HH + h], z);
            ws[r][9 + h] = 1.0f / (1.0f + __expf(-z));
        }
        __syncthreads();

#pragma unroll 2
        for (int r = 0; r < NT; ++r) {
            // phi row as 4x LDS.128 (rows are 64B, 16B-aligned)
            const ulonglong2* ph2 = reinterpret_cast<const ulonglong2*>(&phs[r][0]);
            ulonglong2 qa = ph2[0], qb = ph2[1], qc = ph2[2], qd = ph2[3];
            ull pv[8];
            pv[0]=qa.x; pv[1]=qa.y; pv[2]=qb.x; pv[3]=qb.y;
            pv[4]=qc.x; pv[5]=qc.y; pv[6]=qd.x; pv[7]=qd.y;
            const float* row = &ws[r][0];
#pragma unroll
            for (int k = 0; k < PPT; ++k) {
                float prod = row[wi[k]] * row[wj[k]];
                unsigned int pu = __float_as_uint(prod);
                ull pp;
                asm("mov.b64 %0, {%1, %2};" : "=l"(pp) : "r"(pu), "r"(pu));
#pragma unroll
                for (int w = 0; w < 8; ++w)
                    asm("fma.rn.f32x2 %0, %1, %2, %0;" : "+l"(acc[k][w]) : "l"(pv[w]), "l"(pp));
            }
        }
    }

    ull* outp = &g_part[((size_t)blockIdx.x * NPAIR_PAD + (size_t)tid*PPT) * 8];
#pragma unroll
    for (int k = 0; k < PPT; ++k)
#pragma unroll
        for (int w = 0; w < 8; ++w) outp[k*8 + w] = acc[k][w];
}

// Coalesced parallel compensated cross-block sum.
// warp = one fixed partial q (b = q, q+8, ...), lanes = 32 consecutive e
// -> every LDG is a single 128B line. Combine the 8 partials per e in shared
// memory with the SAME fixed tree as before -> g_tot bitwise identical.
__global__ __launch_bounds__(256) void k_sum(int nblk) {
    __shared__ float smh[8][33], sml[8][33];
    const int l = threadIdx.x & 31;        // lane -> e offset
    const int q = threadIdx.x >> 5;        // warp -> partial index
    const int e0 = blockIdx.x * 32;
    const int e = e0 + l;
    const float* pf = reinterpret_cast<const float*>(g_part);
    float sh = 0.f, sl = 0.f;
    for (int b = q; b < nblk; b += 8) {
        float x = pf[(size_t)b * (NPAIR_PAD*TT) + e];
        float s = sh + x;
        float bb = s - sh;
        float err = (sh - (s - bb)) + (x - bb);
        sh = s; sl += err;
    }
    smh[q][l] = sh; sml[q][l] = sl;
    __syncthreads();
    if (threadIdx.x < 32) {
        dfv a0; a0.h = smh[0][l]; a0.l = sml[0][l];
        dfv a1; a1.h = smh[1][l]; a1.l = sml[1][l];
        dfv a2; a2.h = smh[2][l]; a2.l = sml[2][l];
        dfv a3; a3.h = smh[3][l]; a3.l = sml[3][l];
        dfv a4; a4.h = smh[4][l]; a4.l = sml[4][l];
        dfv a5; a5.h = smh[5][l]; a5.l = sml[5][l];
        dfv a6; a6.h = smh[6][l]; a6.l = sml[6][l];
        dfv a7; a7.h = smh[7][l]; a7.l = sml[7][l];
        dfv b01 = df_add(a0, a1);
        dfv b23 = df_add(a2, a3);
        dfv b45 = df_add(a4, a5);
        dfv b67 = df_add(a6, a7);
        dfv c03 = df_add(b01, b23);
        dfv c47 = df_add(b45, b67);
        dfv tt  = df_add(c03, c47);
        g_tot[e] = make_float2(tt.h, tt.l);
    }
}

#define NF 512

__global__ __launch_bounds__(NF) void k_final(
    const float* __restrict__ epsA, const float* __restrict__ epsB,
    const float* __restrict__ zetA, const float* __restrict__ zetB,
    float* __restrict__ out)
{
    const int t = blockIdx.x;
    const int tid = threadIdx.x;
    __shared__ float Mh[HP1][HP1+1], Ml[HP1][HP1+1];
    __shared__ float Xs[HP1][HP1+1];   // GJ inverse / Newton ping buffer (final lands here)
    __shared__ float Rs[HP1][HP1+1];
    __shared__ float Ts[HP1][HP1+1];   // Newton pong buffer
    __shared__ float rowkb[2][HP1], colkb[2][HP1];   // ping-pong pivot row/col
    __shared__ float bvh[HP1], bvl[HP1], wmv[HP1];
    __shared__ float4 red[NF/32];

    const float eps = __fdiv_rn(epsA[t], epsB[t]);
    const float zet = __fdiv_rn(zetA[t], zetB[t]);

    // Per-thread flat element list for 41x41 sweeps
    int er[4], ec[4];
#pragma unroll
    for (int u = 0; u < 4; ++u) {
        int idx = tid + u*NF;
        if (idx < HP1*HP1) { er[u] = idx / HP1; ec[u] = idx - er[u]*HP1; }
        else { er[u] = -1; ec[u] = 0; }
    }

    // Per-t slice of the cheap outputs
    if (tid == 0) {
        dfv sp = dtot(44*TT + t);
        out[O_BG1 + t] = df_addf(sp, 1.0f).h;
        out[O_KAP + t] = df_addf(sp, 1000.0f).h;
        out[O_NU  + t] = df_addf(sp, 100.0f).h;
        out[O_ZA  + t] = zetA[t] + 20.5f;
        out[O_EA  + t] = df_addf(df_mulf(sp, 0.5f), epsA[t]).h;
        dfv s2; s2.h = 0.f; s2.l = 0.f;
        for (int v = t + 1; v < TT; ++v) s2 = df_add(s2, dtot(44*TT + v));
        out[O_BG2 + t] = df_addf(s2, 1.0f).h;
    }
    if (tid >= 32 && tid < 32 + DD) {
        int i = tid - 32;
        dfv kap = df_addf(dtot(44*TT + t), 1000.0f);
        out[O_MU + i*TT + t] = __fdiv_rn(dtot(pairM1(i,8)*TT + t).h, kap.h);
    }
    if (tid >= 64 && tid < 128) {
        int i = (tid - 64) >> 3, j = (tid - 64) & 7;
        dfv kap = df_addf(dtot(44*TT + t), 1000.0f);
        dfv t12i = dtot(pairM1(i,8)*TT + t);
        dfv t12j = dtot(pairM1(j,8)*TT + t);
        int lo = i < j ? i : j, hi = i < j ? j : i;
        dfv Sij = dtot(pairM1(lo,hi)*TT + t);
        dfv num = df_mul(t12i, t12j);
        float q0 = __fdiv_rn(num.h, kap.h);
        dfv rem = df_add(num, df_mulf(kap, -q0));
        float q1 = __fdiv_rn(rem.h + rem.l, kap.h);
        dfv s1 = two_sum(Sij.h, -q0);
        float psi = s1.h + (s1.l + Sij.l - q1) + ((i==j) ? 500.0f : 0.0f);
        out[O_PSI + i*DD*TT + j*TT + t] = psi;
    }

    // Build M (double-float): M = eps*A + zet*I ; Xs = fp32 copy for in-place GJ.
    // Also seed the k=0 pivot row/col buffers (parity 0).
#pragma unroll
    for (int u = 0; u < 4; ++u) {
        if (er[u] < 0) continue;
        int i = er[u], j = ec[u];
        int a = lmap(i), b = lmap(j);
        int lo = a < b ? a : b, hi = a < b ? b : a;
        dfv A = dtot(pairM2(lo, hi)*TT + t);
        dfv M = df_mulf(A, eps);
        if (i == j) M = df_addf(M, zet);
        Mh[i][j] = M.h; Ml[i][j] = M.l;
        Xs[i][j] = M.h;
        if (i == 0) rowkb[0][j] = M.h;
        if (j == 0) colkb[0][i] = M.h;
    }
    __syncthreads();

    // In-place pivot-free Gauss-Jordan inversion (M is SPD), ONE sync/iter:
    // sweep k also mirrors the freshly-computed row/col k+1 into ping-pong buffers.
    for (int k = 0; k < HP1; ++k) {
        const int pb = k & 1, nb = pb ^ 1;
        float ip = __frcp_rn(rowkb[pb][k]);
#pragma unroll
        for (int u = 0; u < 4; ++u) {
            if (er[u] < 0) continue;
            int r = er[u], c = ec[u];
            float v;
            if (r == k) {
                v = (c == k) ? ip : rowkb[pb][c] * ip;
            } else {
                float f = colkb[pb][r] * ip;
                v = (c == k) ? -f : fmaf(-f, rowkb[pb][c], Xs[r][c]);
            }
            Xs[r][c] = v;
            if (r == k + 1) rowkb[nb][c] = v;
            if (c == k + 1) colkb[nb][r] = v;
        }
        __syncthreads();
    }

    // 2 Newton steps, ping-pong (2 syncs/iter): R = I - M*X ; Xnext = X + X*R
    {
        float (*Xc)[HP1+1] = Xs;
        float (*Xn)[HP1+1] = Ts;
        for (int it = 0; it < 2; ++it) {
#pragma unroll
            for (int u = 0; u < 4; ++u) {
                if (er[u] < 0) continue;
                int i = er[u], j = ec[u];
                float sh = 0.f, sl = 0.f;
                for (int k = 0; k < HP1; ++k) {
                    float mh = Mh[i][k], x = Xc[k][j];
                    float p = mh * x;
                    float e = fmaf(mh, x, -p);
                    e = fmaf(Ml[i][k], x, e);
                    float s = sh + p;
                    float bb = s - sh;
                    float err = (sh - (s - bb)) + (p - bb);
                    sh = s; sl += err + e;
                }
                float d = (i==j) ? 1.f : 0.f;
                dfv r = two_sum(d, -sh);
                Rs[i][j] = r.h + (r.l - sl);
            }
            __syncthreads();
#pragma unroll
            for (int u = 0; u < 4; ++u) {
                if (er[u] < 0) continue;
                int i = er[u], j = ec[u];
                float s = Xc[i][j];
                for (int k = 0; k < HP1; ++k) s = fmaf(Xc[i][k], Rs[k][j], s);
                Xn[i][j] = s;
            }
            __syncthreads();
            float (*tmp)[HP1+1] = Xc; Xc = Xn; Xn = tmp;
        }
        // after 2 iters the final inverse is back in Xs
    }

    // b vector (df) and WMv = zet * X b  (df dot)
    if (tid < HP1) {
        dfv b = dtot(pairM2(lmap(tid), HP1)*TT + t);
        bvh[tid] = b.h; bvl[tid] = b.l;
    }
    __syncthreads();
    if (tid < HP1) {
        float sh = 0.f, sl = 0.f;
        for (int j = 0; j < HP1; ++j) {
            float x = Xs[tid][j];
            float p = x * bvh[j];
            float e = fmaf(x, bvh[j], -p);
            e = fmaf(x, bvl[j], e);
            float s = sh + p;
            float bb = s - sh;
            float err = (sh - (s - bb)) + (p - bb);
            sh = s; sl += err + e;
        }
        float wm = zet * (sh + sl);
        wmv[tid] = wm;
        out[O_WM + t*HP1 + tid] = wm;
    }
    __syncthreads();

#pragma unroll
    for (int u = 0; u < 4; ++u) {
        if (er[u] < 0) continue;
        out[O_WS + t*HP1*HP1 + er[u]*HP1 + ec[u]] = Xs[er[u]][ec[u]];
    }

    // Epilogue partials: t2e = sum_ij M_ij X_ji ; wMw = sum_ij wm_i M_ij wm_j
    float ah = 0.f, al = 0.f, bh2 = 0.f, bl2 = 0.f;
#pragma unroll
    for (int u = 0; u < 4; ++u) {
        if (er[u] < 0) continue;
        int i = er[u], j = ec[u];
        float mh = Mh[i][j], ml = Ml[i][j];
        float x = Xs[j][i];
        float p = mh * x;
        float e = fmaf(mh, x, -p);
        e = fmaf(ml, x, e);
        { float s = ah + p; float bb = s - ah;
          float err = (ah - (s - bb)) + (p - bb);
          ah = s; al += err + e; }
        float w2 = wmv[i] * wmv[j];
        float p2 = mh * w2;
        float e2 = fmaf(mh, w2, -p2);
        e2 = fmaf(ml, w2, e2);
        { float s = bh2 + p2; float bb = s - bh2;
          float err = (bh2 - (s - bb)) + (p2 - bb);
          bh2 = s; bl2 += err + e2; }
    }
    {
        dfv a; a.h = ah; a.l = al;
        dfv b; b.h = bh2; b.l = bl2;
#pragma unroll
        for (int off = 16; off > 0; off >>= 1) {
            float xh = __shfl_down_sync(0xffffffffu, a.h, off);
            float xl = __shfl_down_sync(0xffffffffu, a.l, off);
            float yh = __shfl_down_sync(0xffffffffu, b.h, off);
            float yl = __shfl_down_sync(0xffffffffu, b.l, off);
            dfv xa; xa.h = xh; xa.l = xl;
            dfv yb; yb.h = yh; yb.l = yl;
            a = df_add(a, xa);
            b = df_add(b, yb);
        }
        if ((tid & 31) == 0) red[tid >> 5] = make_float4(a.h, a.l, b.h, b.l);
    }
    __syncthreads();

    if (tid == 0) {
        dfv t2e; t2e.h = 0.f; t2e.l = 0.f;
        dfv wMw; wMw.h = 0.f; wMw.l = 0.f;
        for (int k = 0; k < NF/32; ++k) {
            float4 v = red[k];
            dfv a; a.h = v.x; a.l = v.y;
            dfv b; b.h = v.z; b.l = v.w;
            t2e = df_add(t2e, a);
            wMw = df_add(wMw, b);
        }
        dfv trX; trX.h = 0.f; trX.l = 0.f;
        dfv wm2; wm2.h = 0.f; wm2.l = 0.f;
        dfv wb;  wb.h = 0.f;  wb.l = 0.f;
        for (int i = 0; i < HP1; ++i) {
            trX = df_addf(trX, Xs[i][i]);
            float w = wmv[i];
            dfv ww; ww.h = w * w; ww.l = fmaf(w, w, -ww.h);
            wm2 = df_add(wm2, ww);
            dfv bvi; bvi.h = bvh[i]; bvi.l = bvl[i];
            wb = df_add(wb, df_mulf(bvi, w));
        }
        float inv_eps = __frcp_rn(eps);
        dfv t2 = df_mulf(df_add(t2e, df_mulf(trX, -zet)), inv_eps);
        dfv qf = df_mulf(df_add(wMw, df_mulf(wm2, -zet)), inv_eps);
        dfv cc = dtot(947*TT + t);
        dfv t1 = df_add(df_add(cc, df_mulf(wb, -2.0f)), qf);
        dfv zb = df_addf(df_mulf(df_add(wm2, trX), 0.5f), zetB[t]);
        dfv eb = df_addf(df_mulf(df_add(t1, t2), 0.5f), epsB[t]);
        out[O_ZB + t] = zb.h;
        out[O_EB + t] = eb.h;
    }
}

extern "C" void kernel_launch(void* const* d_in, const int* in_sizes, int n_in,
                              void* d_out, int out_size) {
    const float* Phi  = (const float*)d_in[1];
    const float* Xin  = (const float*)d_in[2];
    const float* Yout = (const float*)d_in[3];
    const float* W    = (const float*)d_in[4];
    const float* B    = (const float*)d_in[5];
    const float* eA   = (const float*)d_in[6];
    const float* eB   = (const float*)d_in[7];
    const float* zA   = (const float*)d_in[8];
    const float* zB   = (const float*)d_in[9];
    int n_total = in_sizes[1] / TT;

    k_reduce<<<NBLK, NTHREADS>>>(Phi, Xin, Yout, W, B, n_total);
    k_sum<<<(NPAIR_PAD*TT)/32, 256>>>(NBLK);
    k_final<<<TT, NF>>>(eA, eB, zA, zB, (float*)d_out);
}